// round 1
// baseline (speedup 1.0000x reference)
#include <cuda_runtime.h>
#include <math.h>

#define T_  100
#define B_  64
#define I_  256
#define H_  512
#define TH  (3*H_)        // 1536
#define KTOT (I_+H_)      // 768
#define KC  64
#define NCHUNK (KTOT/KC)  // 12

// Scratch (device globals: allocation-free rule)
__device__ float g_f[(size_t)T_*B_*H_];    // f gate per step     (13.1 MB)
__device__ float g_D[(size_t)T_*B_*TH];    // d, then F*d         (39.3 MB)

__device__ __forceinline__ float sigf(float x) {
    return 1.0f / (1.0f + __expf(-x));
}

// ---------------------------------------------------------------------------
// Phase 1: one LSTM step. 128 CTAs x 256 threads.
// CTA owns 4 h-indices -> 16 gate rows (i,f,g,o x 4). Computes
// gates[64 batches, 16 rows] = z @ Wslice^T + bias, then elementwise update.
// z = concat(x_t, h_{t-1}) staged transposed in smem; W chunk-streamed.
// ---------------------------------------------------------------------------
__global__ __launch_bounds__(256) void step_kernel(
    int t,
    const float* __restrict__ input,
    const float* __restrict__ init_h,
    const float* __restrict__ init_c,
    const float* __restrict__ w_ih,
    const float* __restrict__ w_hh,
    const float* __restrict__ b_ih,
    const float* __restrict__ b_hh,
    float* __restrict__ out_h,
    float* __restrict__ out_c)
{
    __shared__ __align__(16) float zsm[2][KC][B_];     // 32 KB, transposed [k][b]
    __shared__ float wsm[2][16][KC + 1];               // 8.3 KB (pad avoids bank clash)
    __shared__ float gsm[16][B_];                      // 4 KB
    __shared__ float bsm[16];

    const int tid   = threadIdx.x;
    const int cta   = blockIdx.x;          // 0..127
    const int hbase = cta * 4;

    const float* hprev = (t == 0) ? init_h : (out_h + (size_t)(t - 1) * B_ * H_);
    const float* xt    = input + (size_t)t * B_ * I_;

    if (tid < 16) {
        int row = (tid >> 2) * H_ + hbase + (tid & 3);
        bsm[tid] = b_ih[row] + b_hh[row];
    }

    auto stage = [&](int c, int buf) {
        const int kc0 = c * KC;
        // z: thread -> b = tid&63 (lanes hit distinct banks), q = tid>>6, 16 k's each
        {
            const int b = tid & 63, q = tid >> 6;
            #pragma unroll
            for (int m = 0; m < 4; m++) {
                int kl = q * 16 + m * 4;
                int kg = kc0 + kl;
                float4 v;
                if (kg < I_) v = *(const float4*)(xt + (size_t)b * I_ + kg);
                else         v = *(const float4*)(hprev + (size_t)b * H_ + (kg - I_));
                zsm[buf][kl + 0][b] = v.x;
                zsm[buf][kl + 1][b] = v.y;
                zsm[buf][kl + 2][b] = v.z;
                zsm[buf][kl + 3][b] = v.w;
            }
        }
        // W chunk: 16 rows x 64 k = 1024 floats, one float4 per thread
        {
            int idx = tid * 4;
            int r = idx >> 6, kl = idx & 63;
            int row = (r >> 2) * H_ + hbase + (r & 3);
            int kg = kc0 + kl;
            float4 wv;
            if (kg < I_) wv = *(const float4*)(w_ih + (size_t)row * I_ + kg);
            else         wv = *(const float4*)(w_hh + (size_t)row * H_ + (kg - I_));
            wsm[buf][r][kl + 0] = wv.x;
            wsm[buf][r][kl + 1] = wv.y;
            wsm[buf][r][kl + 2] = wv.z;
            wsm[buf][r][kl + 3] = wv.w;
        }
    };

    const int r  = tid >> 4;     // gate-row within CTA (0..15)
    const int bg = tid & 15;     // batch group (4 batches)
    float acc0 = 0.f, acc1 = 0.f, acc2 = 0.f, acc3 = 0.f;

    stage(0, 0);
    __syncthreads();
    for (int c = 0; c < NCHUNK; c++) {
        const int buf = c & 1;
        if (c + 1 < NCHUNK) stage(c + 1, buf ^ 1);
        #pragma unroll
        for (int k = 0; k < KC; k++) {
            float  w = wsm[buf][r][k];
            float4 z = *(const float4*)&zsm[buf][k][bg * 4];
            acc0 = fmaf(z.x, w, acc0);
            acc1 = fmaf(z.y, w, acc1);
            acc2 = fmaf(z.z, w, acc2);
            acc3 = fmaf(z.w, w, acc3);
        }
        __syncthreads();
    }

    // exchange gates through smem (add bias here)
    {
        float bb = bsm[r];
        gsm[r][bg * 4 + 0] = acc0 + bb;
        gsm[r][bg * 4 + 1] = acc1 + bb;
        gsm[r][bg * 4 + 2] = acc2 + bb;
        gsm[r][bg * 4 + 3] = acc3 + bb;
    }
    __syncthreads();

    // elementwise update: one (b, h) per thread
    {
        const int b  = tid >> 2;
        const int hl = tid & 3;
        const int h  = hbase + hl;

        float gi = gsm[0  + hl][b];
        float gf = gsm[4  + hl][b];
        float gg = gsm[8  + hl][b];
        float go = gsm[12 + hl][b];

        float cp = (t == 0 ? init_c : out_c)[b * H_ + h];
        float i_ = sigf(gi);
        float f_ = sigf(gf);
        float g_ = tanhf(gg);
        float o_ = sigf(go);

        float cy = f_ * cp + i_ * g_;
        float hy = o_ * tanhf(cy);

        out_c[b * H_ + h] = cy;
        out_h[(size_t)t * B_ * H_ + (size_t)b * H_ + h] = hy;
        g_f[((size_t)t * B_ + b) * H_ + h] = f_;

        size_t dbase = ((size_t)t * B_ + b) * TH;
        g_D[dbase + h]          = g_ * i_ * (1.f - i_);   // d_i
        g_D[dbase + H_ + h]     = cp * f_ * (1.f - f_);   // d_f
        g_D[dbase + 2 * H_ + h] = i_ * (1.f - g_ * g_);   // d_g
    }
}

// ---------------------------------------------------------------------------
// Phase 2: suffix product of f and in-place scale of d -> D = (prod f_{s>t}) d_t
// Also accumulates ev_b = sum_t D[t]. One thread per (b,h), fully coalesced.
// ---------------------------------------------------------------------------
__global__ __launch_bounds__(256) void scan_kernel(float* __restrict__ out_evb)
{
    const int u = blockIdx.x * 256 + threadIdx.x;   // 0..32767
    const int b = u >> 9, h = u & (H_ - 1);
    float coef = 1.f, si = 0.f, sf = 0.f, sg = 0.f;
    for (int t = T_ - 1; t >= 0; t--) {
        float f = g_f[((size_t)t * B_ + b) * H_ + h];
        size_t dbase = ((size_t)t * B_ + b) * TH;
        float di = g_D[dbase + h]          * coef;
        float df = g_D[dbase + H_ + h]     * coef;
        float dg = g_D[dbase + 2 * H_ + h] * coef;
        g_D[dbase + h]          = di;
        g_D[dbase + H_ + h]     = df;
        g_D[dbase + 2 * H_ + h] = dg;
        si += di; sf += df; sg += dg;
        coef *= f;
    }
    out_evb[b * TH + h]          = si;
    out_evb[b * TH + H_ + h]     = sf;
    out_evb[b * TH + 2 * H_ + h] = sg;
}

// ---------------------------------------------------------------------------
// Phase 3: per-batch outer-product GEMM:  C[b] = D_b^T (3H x T) @ Z_b (T x N)
// mode 0: Z = x_t (N = I),  mode 1: Z = h_{t-1} (N = H).
// CTA: (itile 64, jtile 64) of one batch; 256 thr, 4x4 register tile, K = T = 100.
// ---------------------------------------------------------------------------
__global__ __launch_bounds__(256) void outer_kernel(
    const float* __restrict__ src,      // input (mode 0); unused in mode 1
    const float* __restrict__ init_h,
    const float* __restrict__ out_h,
    float* __restrict__ outC,
    int N, int mode)
{
    extern __shared__ __align__(16) float sm[];
    float* Dsm = sm;            // [T_][64]
    float* Xsm = sm + T_ * 64;  // [T_][64]

    const int tid = threadIdx.x;
    const int itile = blockIdx.x, jtile = blockIdx.y, b = blockIdx.z;
    const int ibase = itile * 64, jbase = jtile * 64;

    for (int idx = tid; idx < T_ * 16; idx += 256) {
        int t = idx >> 4, j4 = (idx & 15) * 4;
        *(float4*)&Dsm[t * 64 + j4] =
            *(const float4*)(g_D + ((size_t)t * B_ + b) * TH + jbase + j4);
    }
    for (int idx = tid; idx < T_ * 16; idx += 256) {
        int t = idx >> 4, i4 = (idx & 15) * 4;
        const float* p;
        if (mode == 0) p = src + ((size_t)t * B_ + b) * I_ + ibase + i4;
        else p = (t == 0) ? (init_h + (size_t)b * H_ + ibase + i4)
                          : (out_h + ((size_t)(t - 1) * B_ + b) * H_ + ibase + i4);
        *(float4*)&Xsm[t * 64 + i4] = *(const float4*)p;
    }
    __syncthreads();

    const int jg = tid >> 4, ig = tid & 15;
    float a00=0,a01=0,a02=0,a03=0, a10=0,a11=0,a12=0,a13=0;
    float a20=0,a21=0,a22=0,a23=0, a30=0,a31=0,a32=0,a33=0;

    #pragma unroll 4
    for (int t = 0; t < T_; t++) {
        float4 d = *(const float4*)&Dsm[t * 64 + jg * 4];
        float4 x = *(const float4*)&Xsm[t * 64 + ig * 4];
        a00 = fmaf(d.x, x.x, a00); a01 = fmaf(d.x, x.y, a01);
        a02 = fmaf(d.x, x.z, a02); a03 = fmaf(d.x, x.w, a03);
        a10 = fmaf(d.y, x.x, a10); a11 = fmaf(d.y, x.y, a11);
        a12 = fmaf(d.y, x.z, a12); a13 = fmaf(d.y, x.w, a13);
        a20 = fmaf(d.z, x.x, a20); a21 = fmaf(d.z, x.y, a21);
        a22 = fmaf(d.z, x.z, a22); a23 = fmaf(d.z, x.w, a23);
        a30 = fmaf(d.w, x.x, a30); a31 = fmaf(d.w, x.y, a31);
        a32 = fmaf(d.w, x.z, a32); a33 = fmaf(d.w, x.w, a33);
    }

    size_t obase = (size_t)b * TH * N + ibase + ig * 4;
    int j0 = jbase + jg * 4;
    *(float4*)(outC + obase + (size_t)(j0 + 0) * N) = make_float4(a00, a01, a02, a03);
    *(float4*)(outC + obase + (size_t)(j0 + 1) * N) = make_float4(a10, a11, a12, a13);
    *(float4*)(outC + obase + (size_t)(j0 + 2) * N) = make_float4(a20, a21, a22, a23);
    *(float4*)(outC + obase + (size_t)(j0 + 3) * N) = make_float4(a30, a31, a32, a33);
}

// ---------------------------------------------------------------------------

extern "C" void kernel_launch(void* const* d_in, const int* in_sizes, int n_in,
                              void* d_out, int out_size)
{
    const float* input = (const float*)d_in[0];
    const float* ih    = (const float*)d_in[1];
    const float* ic    = (const float*)d_in[2];
    const float* wih   = (const float*)d_in[3];
    const float* whh   = (const float*)d_in[4];
    const float* bih   = (const float*)d_in[5];
    const float* bhh   = (const float*)d_in[6];

    float* out       = (float*)d_out;
    float* out_h     = out;                                   // [T,B,H]
    float* out_c     = out_h  + (size_t)T_ * B_ * H_;         // [B,H]
    float* out_evih  = out_c  + (size_t)B_ * H_;              // [B,3H,I]
    float* out_evhh  = out_evih + (size_t)B_ * TH * I_;       // [B,3H,H]
    float* out_evb   = out_evhh + (size_t)B_ * TH * H_;       // [B,3H,1]

    cudaFuncSetAttribute(outer_kernel,
                         cudaFuncAttributeMaxDynamicSharedMemorySize,
                         2 * T_ * 64 * (int)sizeof(float));

    for (int t = 0; t < T_; t++)
        step_kernel<<<128, 256>>>(t, input, ih, ic, wih, whh, bih, bhh,
                                  out_h, out_c);

    scan_kernel<<<128, 256>>>(out_evb);

    const int smem3 = 2 * T_ * 64 * (int)sizeof(float);
    outer_kernel<<<dim3(I_ / 64, TH / 64, B_), 256, smem3>>>(
        input, ih, out_h, out_evih, I_, 0);
    outer_kernel<<<dim3(H_ / 64, TH / 64, B_), 256, smem3>>>(
        input, ih, out_h, out_evhh, H_, 1);
}

// round 2
// speedup vs baseline: 1.6274x; 1.6274x over previous
#include <cuda_runtime.h>
#include <math.h>

#define T_  100
#define B_  64
#define I_  256
#define H_  512
#define G4  2048            // 4*H
#define TH  1536            // 3*H
#define KSPLIT 4

typedef unsigned long long ull;

// ------------------------- scratch (device globals) -------------------------
__device__ float g_GX[(size_t)T_ * B_ * G4];          // x@Wih^T + biases  [t][b][row]
__device__ float g_P [(size_t)KSPLIT * B_ * G4];      // h@Whh^T partials  [ks][b][row]
__device__ float g_hT[(size_t)(T_ + 1) * H_ * B_];    // h transposed      [slot][k][b]
__device__ float g_f [(size_t)T_ * B_ * H_];          // forget gates      [t][b][h]
__device__ float g_D [(size_t)T_ * B_ * TH];          // d, then suffix(f)*d

// ------------------------- f32x2 helpers -----------------------------------
__device__ __forceinline__ ull dup2(float x) {
    ull r; asm("mov.b64 %0, {%1, %1};" : "=l"(r) : "f"(x)); return r;
}
__device__ __forceinline__ void fma2(ull& a, ull x, ull y) {
    asm("fma.rn.f32x2 %0, %1, %2, %0;" : "+l"(a) : "l"(x), "l"(y));
}
__device__ __forceinline__ float2 unp(ull v) {
    float2 r; asm("mov.b64 {%0, %1}, %2;" : "=f"(r.x), "=f"(r.y) : "l"(v)); return r;
}
__device__ __forceinline__ float sigf(float x) { return 1.0f / (1.0f + __expf(-x)); }

// ------------------------- init: transpose initial_h ------------------------
__global__ __launch_bounds__(256) void init_hT_kernel(const float* __restrict__ ih)
{
    int u = blockIdx.x * 256 + threadIdx.x;      // 32768 threads
    int h = u & (H_ - 1), b = u >> 9;
    g_hT[(size_t)h * B_ + b] = ih[b * H_ + h];
}

// ---------------------------------------------------------------------------
// GX kernel: GX[t][b][row] = sum_k x[t][b][k]*Wih[row][k] + bih[row]+bhh[row]
// grid (32 rowtiles, T).  CTA: 64 rows x 64 b, K=256 in 4 chunks of 64.
// f32x2: accumulator pairs along b; W duplicated into smem at staging.
// ---------------------------------------------------------------------------
__global__ __launch_bounds__(256) void gx_kernel(
    const float* __restrict__ x, const float* __restrict__ wih,
    const float* __restrict__ bih, const float* __restrict__ bhh)
{
    extern __shared__ __align__(16) char smraw[];
    float* zs = (float*)smraw;                    // [2][64][64] floats (32KB)
    ull*   ws = (ull*)(smraw + 2 * 64 * 64 * 4);  // [2][64][64] ull   (64KB)

    const int tid = threadIdx.x;
    const int rowbase = blockIdx.x * 64;
    const int t = blockIdx.y;
    const float* xt = x + (size_t)t * B_ * I_;

    const int zb_ = tid & 63, zq = tid >> 6;      // z staging map (transpose)
    const int wr_ = tid & 63, wq = tid >> 6;      // w staging map

    float4 zr[4], wr[4];
    auto stage_load = [&](int c) {
        const int kc0 = c * 64;
        #pragma unroll
        for (int m = 0; m < 4; m++) {
            int kl = zq * 16 + m * 4;
            zr[m] = *(const float4*)(xt + (size_t)zb_ * I_ + kc0 + kl);
            wr[m] = *(const float4*)(wih + (size_t)(rowbase + wr_) * I_ + kc0 + kl);
        }
    };
    auto stage_store = [&](int buf) {
        float* zd = zs + buf * 4096;
        ull*   wd = ws + buf * 4096;
        #pragma unroll
        for (int m = 0; m < 4; m++) {
            int kl = zq * 16 + m * 4;
            zd[(kl + 0) * 64 + zb_] = zr[m].x;
            zd[(kl + 1) * 64 + zb_] = zr[m].y;
            zd[(kl + 2) * 64 + zb_] = zr[m].z;
            zd[(kl + 3) * 64 + zb_] = zr[m].w;
            wd[(kl + 0) * 64 + wr_] = dup2(wr[m].x);
            wd[(kl + 1) * 64 + wr_] = dup2(wr[m].y);
            wd[(kl + 2) * 64 + wr_] = dup2(wr[m].z);
            wd[(kl + 3) * 64 + wr_] = dup2(wr[m].w);
        }
    };

    const int ig = tid & 15, jg = tid >> 4;
    ull a00=0,a01=0,a10=0,a11=0,a20=0,a21=0,a30=0,a31=0;

    stage_load(0); stage_store(0); __syncthreads();
    for (int c = 0; c < 4; c++) {
        const int buf = c & 1;
        if (c + 1 < 4) stage_load(c + 1);
        const float* zbp = zs + buf * 4096;
        const ull*   wbp = ws + buf * 4096;
        #pragma unroll 8
        for (int k = 0; k < 64; k++) {
            ulonglong2 zz  = *(const ulonglong2*)&zbp[k * 64 + ig * 4];
            ulonglong2 w01 = *(const ulonglong2*)&wbp[k * 64 + jg * 4];
            ulonglong2 w23 = *(const ulonglong2*)&wbp[k * 64 + jg * 4 + 2];
            fma2(a00, w01.x, zz.x); fma2(a01, w01.x, zz.y);
            fma2(a10, w01.y, zz.x); fma2(a11, w01.y, zz.y);
            fma2(a20, w23.x, zz.x); fma2(a21, w23.x, zz.y);
            fma2(a30, w23.y, zz.x); fma2(a31, w23.y, zz.y);
        }
        __syncthreads();
        if (c + 1 < 4) { stage_store(buf ^ 1); __syncthreads(); }
    }

    int r0 = rowbase + jg * 4;
    float bs0 = bih[r0+0] + bhh[r0+0], bs1 = bih[r0+1] + bhh[r0+1];
    float bs2 = bih[r0+2] + bhh[r0+2], bs3 = bih[r0+3] + bhh[r0+3];
    float2 u00=unp(a00),u01=unp(a01),u10=unp(a10),u11=unp(a11);
    float2 u20=unp(a20),u21=unp(a21),u30=unp(a30),u31=unp(a31);
    float vx[4][4] = {{u00.x,u10.x,u20.x,u30.x},{u00.y,u10.y,u20.y,u30.y},
                      {u01.x,u11.x,u21.x,u31.x},{u01.y,u11.y,u21.y,u31.y}};
    #pragma unroll
    for (int bl = 0; bl < 4; bl++) {
        float4 v = make_float4(vx[bl][0]+bs0, vx[bl][1]+bs1, vx[bl][2]+bs2, vx[bl][3]+bs3);
        *(float4*)(g_GX + ((size_t)t * B_ + ig * 4 + bl) * G4 + r0) = v;
    }
}

// ---------------------------------------------------------------------------
// hh kernel: P[ks][b][row] = sum_{k in split} hT[k][b] * Whh[row][k]
// grid (32 rowtiles, 4 ksplits).  CTA: 64 rows x 64 b, K-range 128 (2 chunks).
// z staging is a straight coalesced copy (g_hT already [k][b]).
// ---------------------------------------------------------------------------
__global__ __launch_bounds__(256) void hh_kernel(int t, const float* __restrict__ whh)
{
    extern __shared__ __align__(16) char smraw[];
    float* zs = (float*)smraw;
    ull*   ws = (ull*)(smraw + 2 * 64 * 64 * 4);

    const int tid = threadIdx.x;
    const int rowbase = blockIdx.x * 64;
    const int kbase = blockIdx.y * 128;
    const float* hT = g_hT + (size_t)t * H_ * B_;

    const int zk = tid >> 4, zb4 = (tid & 15) * 4;  // copy map (coalesced)
    const int wr_ = tid & 63, wq = tid >> 6;

    float4 zr[4], wr[4];
    auto stage_load = [&](int c) {
        const int kc0 = kbase + c * 64;
        #pragma unroll
        for (int m = 0; m < 4; m++) {
            zr[m] = *(const float4*)(hT + (size_t)(kc0 + zk + m * 16) * B_ + zb4);
            int kl = wq * 16 + m * 4;
            wr[m] = *(const float4*)(whh + (size_t)(rowbase + wr_) * H_ + kc0 + kl);
        }
    };
    auto stage_store = [&](int buf) {
        float* zd = zs + buf * 4096;
        ull*   wd = ws + buf * 4096;
        #pragma unroll
        for (int m = 0; m < 4; m++) {
            *(float4*)&zd[(zk + m * 16) * 64 + zb4] = zr[m];
            int kl = wq * 16 + m * 4;
            wd[(kl + 0) * 64 + wr_] = dup2(wr[m].x);
            wd[(kl + 1) * 64 + wr_] = dup2(wr[m].y);
            wd[(kl + 2) * 64 + wr_] = dup2(wr[m].z);
            wd[(kl + 3) * 64 + wr_] = dup2(wr[m].w);
        }
    };

    const int ig = tid & 15, jg = tid >> 4;
    ull a00=0,a01=0,a10=0,a11=0,a20=0,a21=0,a30=0,a31=0;

    stage_load(0); stage_store(0); __syncthreads();
    for (int c = 0; c < 2; c++) {
        const int buf = c & 1;
        if (c + 1 < 2) stage_load(c + 1);
        const float* zbp = zs + buf * 4096;
        const ull*   wbp = ws + buf * 4096;
        #pragma unroll 8
        for (int k = 0; k < 64; k++) {
            ulonglong2 zz  = *(const ulonglong2*)&zbp[k * 64 + ig * 4];
            ulonglong2 w01 = *(const ulonglong2*)&wbp[k * 64 + jg * 4];
            ulonglong2 w23 = *(const ulonglong2*)&wbp[k * 64 + jg * 4 + 2];
            fma2(a00, w01.x, zz.x); fma2(a01, w01.x, zz.y);
            fma2(a10, w01.y, zz.x); fma2(a11, w01.y, zz.y);
            fma2(a20, w23.x, zz.x); fma2(a21, w23.x, zz.y);
            fma2(a30, w23.y, zz.x); fma2(a31, w23.y, zz.y);
        }
        __syncthreads();
        if (c + 1 < 2) { stage_store(buf ^ 1); __syncthreads(); }
    }

    int r0 = rowbase + jg * 4;
    float2 u00=unp(a00),u01=unp(a01),u10=unp(a10),u11=unp(a11);
    float2 u20=unp(a20),u21=unp(a21),u30=unp(a30),u31=unp(a31);
    float vx[4][4] = {{u00.x,u10.x,u20.x,u30.x},{u00.y,u10.y,u20.y,u30.y},
                      {u01.x,u11.x,u21.x,u31.x},{u01.y,u11.y,u21.y,u31.y}};
    #pragma unroll
    for (int bl = 0; bl < 4; bl++) {
        float4 v = make_float4(vx[bl][0], vx[bl][1], vx[bl][2], vx[bl][3]);
        *(float4*)(g_P + ((size_t)blockIdx.y * B_ + ig * 4 + bl) * G4 + r0) = v;
    }
}

// ---------------------------------------------------------------------------
// elementwise: gates = GX + sum P; LSTM update + e-prop d terms.
// thread u -> (b = u>>9, h = u&511): all heavy loads coalesced.
// ---------------------------------------------------------------------------
__global__ __launch_bounds__(256) void ew_kernel(
    int t, const float* __restrict__ init_c,
    float* __restrict__ out_h, float* __restrict__ out_c)
{
    const int u = blockIdx.x * 256 + threadIdx.x;
    const int h = u & (H_ - 1), b = u >> 9;

    const size_t gb = ((size_t)t * B_ + b) * G4;
    float gi = g_GX[gb + h];
    float gf = g_GX[gb + H_ + h];
    float gg = g_GX[gb + 2 * H_ + h];
    float go = g_GX[gb + 3 * H_ + h];
    #pragma unroll
    for (int ks = 0; ks < KSPLIT; ks++) {
        const size_t pb = ((size_t)ks * B_ + b) * G4;
        gi += g_P[pb + h];
        gf += g_P[pb + H_ + h];
        gg += g_P[pb + 2 * H_ + h];
        go += g_P[pb + 3 * H_ + h];
    }

    float cp = (t == 0 ? init_c : out_c)[b * H_ + h];
    float i_ = sigf(gi);
    float f_ = sigf(gf);
    float g_ = tanhf(gg);
    float o_ = sigf(go);

    float cy = f_ * cp + i_ * g_;
    float hy = o_ * tanhf(cy);

    out_c[b * H_ + h] = cy;
    out_h[((size_t)t * B_ + b) * H_ + h] = hy;
    g_f[((size_t)t * B_ + b) * H_ + h] = f_;

    const size_t db = ((size_t)t * B_ + b) * TH;
    g_D[db + h]          = g_ * i_ * (1.f - i_);
    g_D[db + H_ + h]     = cp * f_ * (1.f - f_);
    g_D[db + 2 * H_ + h] = i_ * (1.f - g_ * g_);

    g_hT[((size_t)(t + 1) * H_ + h) * B_ + b] = hy;
}

// ---------------------------------------------------------------------------
// scan: suffix product of f scales d in place; accumulates ev_b.
// ---------------------------------------------------------------------------
__global__ __launch_bounds__(256) void scan_kernel(float* __restrict__ out_evb)
{
    const int u = blockIdx.x * 256 + threadIdx.x;   // 32768
    const int b = u >> 9, h = u & (H_ - 1);
    float coef = 1.f, si = 0.f, sf = 0.f, sg = 0.f;
    for (int t = T_ - 1; t >= 0; t--) {
        float f = g_f[((size_t)t * B_ + b) * H_ + h];
        size_t db = ((size_t)t * B_ + b) * TH;
        float di = g_D[db + h]          * coef;
        float df = g_D[db + H_ + h]     * coef;
        float dg = g_D[db + 2 * H_ + h] * coef;
        g_D[db + h]          = di;
        g_D[db + H_ + h]     = df;
        g_D[db + 2 * H_ + h] = dg;
        si += di; sf += df; sg += dg;
        coef *= f;
    }
    out_evb[b * TH + h]          = si;
    out_evb[b * TH + H_ + h]     = sf;
    out_evb[b * TH + 2 * H_ + h] = sg;
}

// ---------------------------------------------------------------------------
// phase 3: C[b] = D_b^T (3H x T) @ Z_b (T x N), f32x2, D duplicated in smem.
// mode 0: Z = x_t (N=I); mode 1: Z = h_{t-1} (N=H).
// ---------------------------------------------------------------------------
__global__ __launch_bounds__(256) void outer_kernel(
    const float* __restrict__ src, const float* __restrict__ init_h,
    const float* __restrict__ out_h, float* __restrict__ outC, int N, int mode)
{
    extern __shared__ __align__(16) char smraw[];
    ull*   Dsm = (ull*)smraw;                      // [T_][64] dup'd (51.2KB)
    float* Xsm = (float*)(smraw + (size_t)T_ * 64 * 8);  // [T_][64]  (25.6KB)

    const int tid = threadIdx.x;
    const int ibase = blockIdx.x * 64, jbase = blockIdx.y * 64, b = blockIdx.z;

    for (int idx = tid; idx < T_ * 16; idx += 256) {
        int t = idx >> 4, j4 = (idx & 15) * 4;
        float4 v = *(const float4*)(g_D + ((size_t)t * B_ + b) * TH + jbase + j4);
        Dsm[t * 64 + j4 + 0] = dup2(v.x);
        Dsm[t * 64 + j4 + 1] = dup2(v.y);
        Dsm[t * 64 + j4 + 2] = dup2(v.z);
        Dsm[t * 64 + j4 + 3] = dup2(v.w);
    }
    for (int idx = tid; idx < T_ * 16; idx += 256) {
        int t = idx >> 4, i4 = (idx & 15) * 4;
        const float* p;
        if (mode == 0) p = src + ((size_t)t * B_ + b) * I_ + ibase + i4;
        else p = (t == 0) ? (init_h + (size_t)b * H_ + ibase + i4)
                          : (out_h + ((size_t)(t - 1) * B_ + b) * H_ + ibase + i4);
        *(float4*)&Xsm[t * 64 + i4] = *(const float4*)p;
    }
    __syncthreads();

    const int jg = tid >> 4, ig = tid & 15;
    ull a00=0,a01=0,a10=0,a11=0,a20=0,a21=0,a30=0,a31=0;  // a[j][ipair]

    #pragma unroll 4
    for (int t = 0; t < T_; t++) {
        ulonglong2 d01 = *(const ulonglong2*)&Dsm[t * 64 + jg * 4];
        ulonglong2 d23 = *(const ulonglong2*)&Dsm[t * 64 + jg * 4 + 2];
        ulonglong2 xx  = *(const ulonglong2*)&Xsm[t * 64 + ig * 4];
        fma2(a00, d01.x, xx.x); fma2(a01, d01.x, xx.y);
        fma2(a10, d01.y, xx.x); fma2(a11, d01.y, xx.y);
        fma2(a20, d23.x, xx.x); fma2(a21, d23.x, xx.y);
        fma2(a30, d23.y, xx.x); fma2(a31, d23.y, xx.y);
    }

    size_t obase = (size_t)b * TH * N + ibase + ig * 4;
    const int j0 = jbase + jg * 4;
    float2 u;
    float4 v;
    u = unp(a00); v.x = u.x; v.y = u.y; u = unp(a01); v.z = u.x; v.w = u.y;
    *(float4*)(outC + obase + (size_t)(j0 + 0) * N) = v;
    u = unp(a10); v.x = u.x; v.y = u.y; u = unp(a11); v.z = u.x; v.w = u.y;
    *(float4*)(outC + obase + (size_t)(j0 + 1) * N) = v;
    u = unp(a20); v.x = u.x; v.y = u.y; u = unp(a21); v.z = u.x; v.w = u.y;
    *(float4*)(outC + obase + (size_t)(j0 + 2) * N) = v;
    u = unp(a30); v.x = u.x; v.y = u.y; u = unp(a31); v.z = u.x; v.w = u.y;
    *(float4*)(outC + obase + (size_t)(j0 + 3) * N) = v;
}

// ---------------------------------------------------------------------------

extern "C" void kernel_launch(void* const* d_in, const int* in_sizes, int n_in,
                              void* d_out, int out_size)
{
    const float* input = (const float*)d_in[0];
    const float* ih    = (const float*)d_in[1];
    const float* ic    = (const float*)d_in[2];
    const float* wih   = (const float*)d_in[3];
    const float* whh   = (const float*)d_in[4];
    const float* bih   = (const float*)d_in[5];
    const float* bhh   = (const float*)d_in[6];

    float* out      = (float*)d_out;
    float* out_h    = out;                                // [T,B,H]
    float* out_c    = out_h  + (size_t)T_ * B_ * H_;      // [B,H]
    float* out_evih = out_c  + (size_t)B_ * H_;           // [B,3H,I]
    float* out_evhh = out_evih + (size_t)B_ * TH * I_;    // [B,3H,H]
    float* out_evb  = out_evhh + (size_t)B_ * TH * H_;    // [B,3H,1]

    const int smem_gemm  = 2 * 64 * 64 * 4 + 2 * 64 * 64 * 8;   // 98304
    const int smem_outer = T_ * 64 * 8 + T_ * 64 * 4;           // 76800

    cudaFuncSetAttribute(gx_kernel, cudaFuncAttributeMaxDynamicSharedMemorySize, smem_gemm);
    cudaFuncSetAttribute(hh_kernel, cudaFuncAttributeMaxDynamicSharedMemorySize, smem_gemm);
    cudaFuncSetAttribute(outer_kernel, cudaFuncAttributeMaxDynamicSharedMemorySize, smem_outer);

    init_hT_kernel<<<128, 256>>>(ih);
    gx_kernel<<<dim3(32, T_), 256, smem_gemm>>>(input, wih, bih, bhh);

    for (int t = 0; t < T_; t++) {
        hh_kernel<<<dim3(32, KSPLIT), 256, smem_gemm>>>(t, whh);
        ew_kernel<<<128, 256>>>(t, ic, out_h, out_c);
    }

    scan_kernel<<<128, 256>>>(out_evb);

    outer_kernel<<<dim3(I_ / 64, TH / 64, B_), 256, smem_outer>>>(
        input, ih, out_h, out_evih, I_, 0);
    outer_kernel<<<dim3(H_ / 64, TH / 64, B_), 256, smem_outer>>>(
        input, ih, out_h, out_evhh, H_, 1);
}